// round 13
// baseline (speedup 1.0000x reference)
#include <cuda_runtime.h>
#include <cuda_bf16.h>
#include <cstdint>

// Problem constants
#define B_      16
#define N_      8192
#define C_      6
#define K_      512      // NUM_GROUP
#define GS_     32       // GROUP_SIZE
#define BIGF    10000000000.0f
#define FINF    __int_as_float(0x7f800000)

// Output layout (float32, concatenated): neighborhood | center | nn_idx
#define NEIGH_ELEMS   (B_*K_*GS_*C_)   // 1,572,864
#define CENTER_ELEMS  (B_*K_*C_)       // 49,152
#define CENTER_OFF    (NEIGH_ELEMS)
#define NN_OFF        (NEIGH_ELEMS + CENTER_ELEMS)

typedef unsigned long long ull;

// Scratch (device globals; no allocation allowed)
__device__ int g_rep[B_ * K_];
__device__ int g_prog[B_];                       // per-batch published-center count
__device__ __align__(16) float  g_x[B_ * N_];
__device__ __align__(16) float  g_y[B_ * N_];
__device__ __align__(16) float  g_z[B_ * N_];
__device__ __align__(16) float4 g_p4[B_ * N_];   // (x, y, z, |t|^2)

// Packed f32x2 ops (Blackwell sm_100+). Per-lane ops are exact rn fp32.
#define ADD2(o,a,b)   asm("add.rn.f32x2 %0, %1, %2;" : "=l"(o) : "l"(a), "l"(b))
#define MUL2(o,a,b)   asm("mul.rn.f32x2 %0, %1, %2;" : "=l"(o) : "l"(a), "l"(b))
#define FMA2(o,a,b,c) asm("fma.rn.f32x2 %0, %1, %2, %3;" : "=l"(o) : "l"(a), "l"(b), "l"(c))

__device__ __forceinline__ ull pk2(float lo, float hi) {
    return (ull)__float_as_uint(lo) | ((ull)__float_as_uint(hi) << 32);
}
__device__ __forceinline__ float plo(ull v) { return __uint_as_float((unsigned)v); }
__device__ __forceinline__ float phi(ull v) { return __uint_as_float((unsigned)(v >> 32)); }

__device__ __forceinline__ ull umin64(ull a, ull b) { return a < b ? a : b; }

// kNN key: (monotone-float-bits(d2) << 32) | idx. Exact lax.top_k order.
__device__ __forceinline__ ull mkkey(float d2, int j)
{
    int bb = __float_as_int(d2);
    unsigned u = (unsigned)bb ^ ((unsigned)(bb >> 31) | 0x80000000u);
    return ((ull)u << 32) | (unsigned)j;
}

// ---------------------------------------------------------------------------
// Kernel 0: AoS -> SoA xyz (FPS) + float4 (x,y,z,tt) (kNN); zero progress.
// ---------------------------------------------------------------------------
__global__ void prep_kernel(const float* __restrict__ pc)
{
    int j = blockIdx.x * 256 + threadIdx.x;
    if (j < B_) g_prog[j] = 0;
    if (j >= B_ * N_) return;
    const float* p = pc + (size_t)j * C_;
    float px = p[0], py = p[1], pz = p[2];
    g_x[j] = px; g_y[j] = py; g_z[j] = pz;
    float tt = __fadd_rn(__fadd_rn(__fmul_rn(px, px), __fmul_rn(py, py)),
                         __fmul_rn(pz, pz));
    g_p4[j] = make_float4(px, py, pz, tt);
}

// ---------------------------------------------------------------------------
// Fused kernel. CTAs 0..15: FPS (one per batch, R5-proven code + release-
// publish of progress). CTAs 16..1039: kNN for 8 centers each; spin-acquire
// until their centers are published, then proceed (overlapped with FPS).
// Deadlock-free: FPS CTAs have the lowest blockIdx -> wave-1 resident, and
// never wait on kNN CTAs; spins always terminate.
// ---------------------------------------------------------------------------
#define GC 8

__global__ __launch_bounds__(512, 1)
void fused_kernel(const float* __restrict__ pc, float* __restrict__ out)
{
    // FPS smem
    __shared__ unsigned sb[2][16];
    __shared__ unsigned si[2][16];
    // kNN smem
    __shared__ ull   raw[512][2];          // 8 KB scratch (per-center reuse)
    __shared__ ull   cands[GC][256][2];    // 32 KB merged group candidates
    __shared__ float scq[GC][3];
    __shared__ float sqq[GC];
    __shared__ int   scidx[GC];

    const int t = threadIdx.x, lane = t & 31, w = t >> 5;

    if (blockIdx.x < B_) {
        // ================= FPS role (R5 verbatim + publish) =================
        const int b = blockIdx.x;
        const int base = b * N_;

        float xs[16], ys[16], zs[16];
#pragma unroll
        for (int i = 0; i < 16; i++) {
            int j = base + t + i * 512;
            xs[i] = g_x[j]; ys[i] = g_y[j]; zs[i] = g_z[j];
        }
        ull xp[8], yp[8], zp[8];
#pragma unroll
        for (int p = 0; p < 8; p++) {
            xp[p] = pk2(xs[2*p], xs[2*p+1]);
            yp[p] = pk2(ys[2*p], ys[2*p+1]);
            zp[p] = pk2(zs[2*p], zs[2*p+1]);
        }
        float dst[16];
#pragma unroll
        for (int i = 0; i < 16; i++) dst[i] = BIGF;

        float qx = g_x[base], qy = g_y[base], qz = g_z[base];
        int cur = 0;
        int* repb = g_rep + b * K_;

        for (int k = 0; k < K_; k++) {
            if (t == 0) {
                repb[k] = cur;
                // release: orders the rep store before the progress increment
                asm volatile("red.release.gpu.global.add.s32 [%0], 1;"
                             :: "l"(g_prog + b) : "memory");
            }

            const ull nqx = pk2(-qx, -qx), nqy = pk2(-qy, -qy), nqz = pk2(-qz, -qz);
            float bv = -1.0f;
#pragma unroll
            for (int p = 0; p < 8; p++) {
                ull dx, dy, dz, s;
                ADD2(dx, xp[p], nqx);
                ADD2(dy, yp[p], nqy);
                ADD2(dz, zp[p], nqz);
                MUL2(dx, dx, dx);
                MUL2(dy, dy, dy);
                MUL2(dz, dz, dz);
                ADD2(s, dx, dy);
                ADD2(s, s, dz);
                float n0 = fminf(dst[2*p],   plo(s)); dst[2*p]   = n0;
                float n1 = fminf(dst[2*p+1], phi(s)); dst[2*p+1] = n1;
                bv = fmaxf(bv, fmaxf(n0, n1));
            }

            const unsigned mybits = __float_as_uint(bv);
            const unsigned mh = __reduce_max_sync(0xffffffffu, mybits);
            unsigned cnd = 0xffffffffu;
            if (mybits == mh) {
                int fi = 0;
#pragma unroll
                for (int i = 15; i >= 0; i--)
                    if (__float_as_uint(dst[i]) == mybits) fi = i;  // smallest i
                cnd = (unsigned)(t + fi * 512);
            }
            const unsigned mi = __reduce_min_sync(0xffffffffu, cnd);

            const int par = k & 1;
            if (lane == 0) { sb[par][w] = mh; si[par][w] = mi; }
            __syncthreads();

            unsigned v  = (lane < 16) ? sb[par][lane] : 0u;
            unsigned i2 = (lane < 16) ? si[par][lane] : 0xffffffffu;
            unsigned Mh = __reduce_max_sync(0xffffffffu, v);
            unsigned c2 = (v == Mh) ? i2 : 0xffffffffu;
            unsigned Mi = __reduce_min_sync(0xffffffffu, c2);
            cur = (int)Mi;

            qx = g_x[base + cur]; qy = g_y[base + cur]; qz = g_z[base + cur];
        }
        return;
    }

    // ================= kNN role =================
    const int kblk = blockIdx.x - B_;
    const int b    = kblk >> 6;             // 64 kNN CTAs per batch
    const int cen0 = (kblk & 63) * GC;
    const int bbase = b * N_;
    const float4* __restrict__ p4 = g_p4 + bbase;

    if (t < GC) {
        // spin until our 8 centers are published (acquire pairs with release)
        const int need = cen0 + GC;
        int v;
        do {
            asm volatile("ld.acquire.gpu.global.s32 %0, [%1];"
                         : "=r"(v) : "l"(g_prog + b) : "memory");
            if (v < need) __nanosleep(256);
        } while (v < need);

        int idx = g_rep[b * K_ + cen0 + t];
        scidx[t] = idx;
        float4 P = p4[idx];
        scq[t][0] = P.x; scq[t][1] = P.y; scq[t][2] = P.z;
        sqq[t] = __fadd_rn(__fadd_rn(__fmul_rn(P.x, P.x), __fmul_rn(P.y, P.y)),
                           __fmul_rn(P.z, P.z));
    }
    __syncthreads();

    // packed per-center-pair constants: (-2*q of center 2pp, -2*q of 2pp+1)
    ull nqx2[4], nqy2[4], nqz2[4], qq2[4];
#pragma unroll
    for (int pp = 0; pp < 4; pp++) {
        nqx2[pp] = pk2(__fmul_rn(-2.0f, scq[2*pp][0]), __fmul_rn(-2.0f, scq[2*pp+1][0]));
        nqy2[pp] = pk2(__fmul_rn(-2.0f, scq[2*pp][1]), __fmul_rn(-2.0f, scq[2*pp+1][1]));
        nqz2[pp] = pk2(__fmul_rn(-2.0f, scq[2*pp][2]), __fmul_rn(-2.0f, scq[2*pp+1][2]));
        qq2[pp]  = pk2(sqq[2*pp], sqq[2*pp+1]);
    }

    float c0d[GC], c1d[GC];
    int   c0i[GC], c1i[GC];
#pragma unroll
    for (int c = 0; c < GC; c++) {
        c0d[c] = FINF; c1d[c] = FINF; c0i[c] = 0x7fffffff; c1i[c] = 0x7fffffff;
    }

    // main loop: 16 points/thread, j strictly increasing, barrier-free
#pragma unroll 4
    for (int i = 0; i < 16; i++) {
        const int j = i * 512 + t;
        const float4 P = __ldg(p4 + j);
        const ull xx = pk2(P.x, P.x), yy = pk2(P.y, P.y);
        const ull zz = pk2(P.z, P.z), ww = pk2(P.w, P.w);
#pragma unroll
        for (int pp = 0; pp < 4; pp++) {
            ull nd, d;
            MUL2(nd, nqx2[pp], xx);
            FMA2(nd, nqy2[pp], yy, nd);
            FMA2(nd, nqz2[pp], zz, nd);    // nd = -2*dot (exact, per center)
            ADD2(d, qq2[pp], nd);          // qq - 2*dot
            ADD2(d, d, ww);                // + tt
            {   // center 2pp  (branchless sorted-insert, strict < = exact ties)
                const int c = 2 * pp;
                const float da = plo(d);
                const bool lt1 = da < c1d[c], lt0 = da < c0d[c];
                const float n1d = lt0 ? c0d[c] : (lt1 ? da : c1d[c]);
                const int   n1i = lt0 ? c0i[c] : (lt1 ? j  : c1i[c]);
                c0d[c] = lt0 ? da : c0d[c];
                c0i[c] = lt0 ? j  : c0i[c];
                c1d[c] = n1d; c1i[c] = n1i;
            }
            {   // center 2pp+1
                const int c = 2 * pp + 1;
                const float db = phi(d);
                const bool lt1 = db < c1d[c], lt0 = db < c0d[c];
                const float n1d = lt0 ? c0d[c] : (lt1 ? db : c1d[c]);
                const int   n1i = lt0 ? c0i[c] : (lt1 ? j  : c1i[c]);
                c0d[c] = lt0 ? db : c0d[c];
                c0i[c] = lt0 ? j  : c0i[c];
                c1d[c] = n1d; c1i[c] = n1i;
            }
        }
    }

    // pair-merge: group g (<256) = threads (g, g+256); exact sorted-2 merge
#pragma unroll
    for (int c = 0; c < GC; c++) {
        raw[t][0] = mkkey(c0d[c], c0i[c]);
        raw[t][1] = mkkey(c1d[c], c1i[c]);
        __syncthreads();
        if (t < 256) {
            ull a0 = raw[t][0],       a1 = raw[t][1];
            ull b0 = raw[t + 256][0], b1 = raw[t + 256][1];
            ull m0 = umin64(a0, b0);
            ull m1 = (a0 < b0) ? umin64(a1, b0) : umin64(b1, a0);
            cands[c][t][0] = m0;
            cands[c][t][1] = m1;
        }
        __syncthreads();
    }

    // ---- selection: warp w (<GC) -> center w; lane owns groups lane*8+o ----
    if (w < GC) {
        const float qx = scq[w][0], qy = scq[w][1], qz = scq[w][2], qq = sqq[w];

        ull fr[GC];
        unsigned stmask = 0;                   // bit o: second candidate consumed
#pragma unroll
        for (int o = 0; o < GC; o++) fr[o] = cands[w][lane * 8 + o][0];

        int selidx = 0;
        for (int r = 0; r < GS_; r++) {
            ull lm = fr[0]; int ow = 0;
#pragma unroll
            for (int o = 1; o < GC; o++) if (fr[o] < lm) { lm = fr[o]; ow = o; }

            unsigned hi  = (unsigned)(lm >> 32);
            unsigned mh  = __reduce_min_sync(0xffffffffu, hi);
            unsigned cnd = (hi == mh) ? (unsigned)lm : 0xffffffffu;
            unsigned mi  = __reduce_min_sync(0xffffffffu, cnd);
            if (lane == r) selidx = (int)mi;

            if (hi == mh && (unsigned)lm == mi) {  // this lane owned the winner
                const int T = lane * 8 + ow;       // group id (<256)
                ull nv;
                if (!((stmask >> ow) & 1u)) {
                    nv = cands[w][T][1];
                    stmask |= 1u << ow;
                } else {
                    // exact refill over the group's 32-pt stream: min key > lm
                    nv = ~0ull;
                    const ull th = lm;
#pragma unroll 4
                    for (int m = 0; m < 16; m++) {
                        int j2 = m * 512 + T;
                        float4 P = __ldg(p4 + j2);
                        float dot = __fmaf_rn(qz, P.z, __fmaf_rn(qy, P.y, __fmul_rn(qx, P.x)));
                        float d2  = __fadd_rn(__fsub_rn(qq, __fmul_rn(2.0f, dot)), P.w);
                        ull key = mkkey(d2, j2);
                        if (key > th && key < nv) nv = key;
                        int j3 = j2 + 256;
                        float4 Q = __ldg(p4 + j3);
                        float dot2 = __fmaf_rn(qz, Q.z, __fmaf_rn(qy, Q.y, __fmul_rn(qx, Q.x)));
                        float e2   = __fadd_rn(__fsub_rn(qq, __fmul_rn(2.0f, dot2)), Q.w);
                        ull key2 = mkkey(e2, j3);
                        if (key2 > th && key2 < nv) nv = key2;
                    }
                }
#pragma unroll
                for (int o = 0; o < GC; o++) if (o == ow) fr[o] = nv;
            }
        }

        // ---- output: lane L holds rank-L neighbor for center w ----
        const int gcen = b * K_ + cen0 + w;
        const int j = selidx;
        const float4 P = __ldg(p4 + j);
        const float* pf = pc + ((size_t)(bbase + j)) * C_;
        float* o6 = out + ((size_t)gcen * GS_ + lane) * C_;
        o6[0] = __fsub_rn(P.x, qx);
        o6[1] = __fsub_rn(P.y, qy);
        o6[2] = __fsub_rn(P.z, qz);
        o6[3] = pf[3];
        o6[4] = pf[4];
        o6[5] = pf[5];
        out[NN_OFF + (size_t)gcen * GS_ + lane] = (float)j;

        // center row (6 channels) for center w
        if (lane == 0) {
            const float* cf = pc + ((size_t)(bbase + scidx[w])) * C_;
            float* co = out + CENTER_OFF + (size_t)gcen * C_;
            co[0] = qx; co[1] = qy; co[2] = qz;
            co[3] = cf[3]; co[4] = cf[4]; co[5] = cf[5];
        }
    }
}

// ---------------------------------------------------------------------------
extern "C" void kernel_launch(void* const* d_in, const int* in_sizes, int n_in,
                              void* d_out, int out_size)
{
    const float* pc = (const float*)d_in[0];
    float* out = (float*)d_out;

    prep_kernel<<<(B_ * N_ + 255) / 256, 256>>>(pc);
    fused_kernel<<<B_ + B_ * K_ / GC, 512>>>(pc, out);
}

// round 14
// speedup vs baseline: 1.0395x; 1.0395x over previous
#include <cuda_runtime.h>
#include <cuda_bf16.h>
#include <cstdint>

// Problem constants
#define B_      16
#define N_      8192
#define C_      6
#define K_      512      // NUM_GROUP
#define GS_     32       // GROUP_SIZE
#define BIGF    10000000000.0f
#define FINF    __int_as_float(0x7f800000)

// Output layout (float32, concatenated): neighborhood | center | nn_idx
#define NEIGH_ELEMS   (B_*K_*GS_*C_)   // 1,572,864
#define CENTER_ELEMS  (B_*K_*C_)       // 49,152
#define CENTER_OFF    (NEIGH_ELEMS)
#define NN_OFF        (NEIGH_ELEMS + CENTER_ELEMS)

typedef unsigned long long ull;

// Scratch (device globals; no allocation allowed)
__device__ int g_rep[B_ * K_];
__device__ int g_prog[B_];                       // per-batch published-center count
__device__ int g_ticket;                         // dynamic work queue head
__device__ __align__(16) float  g_x[B_ * N_];
__device__ __align__(16) float  g_y[B_ * N_];
__device__ __align__(16) float  g_z[B_ * N_];
__device__ __align__(16) float4 g_p4[B_ * N_];   // (x, y, z, |t|^2)

// Packed f32x2 ops (Blackwell sm_100+). Per-lane ops are exact rn fp32.
#define ADD2(o,a,b)   asm("add.rn.f32x2 %0, %1, %2;" : "=l"(o) : "l"(a), "l"(b))
#define MUL2(o,a,b)   asm("mul.rn.f32x2 %0, %1, %2;" : "=l"(o) : "l"(a), "l"(b))
#define FMA2(o,a,b,c) asm("fma.rn.f32x2 %0, %1, %2, %3;" : "=l"(o) : "l"(a), "l"(b), "l"(c))

__device__ __forceinline__ ull pk2(float lo, float hi) {
    return (ull)__float_as_uint(lo) | ((ull)__float_as_uint(hi) << 32);
}
__device__ __forceinline__ float plo(ull v) { return __uint_as_float((unsigned)v); }
__device__ __forceinline__ float phi(ull v) { return __uint_as_float((unsigned)(v >> 32)); }

__device__ __forceinline__ ull umin64(ull a, ull b) { return a < b ? a : b; }

// kNN key: (monotone-float-bits(d2) << 32) | idx. Exact lax.top_k order.
__device__ __forceinline__ ull mkkey(float d2, int j)
{
    int bb = __float_as_int(d2);
    unsigned u = (unsigned)bb ^ ((unsigned)(bb >> 31) | 0x80000000u);
    return ((ull)u << 32) | (unsigned)j;
}

// ---------------------------------------------------------------------------
// Kernel 0: AoS -> SoA xyz (FPS) + float4 (x,y,z,tt) (kNN); zero sync state.
// ---------------------------------------------------------------------------
__global__ void prep_kernel(const float* __restrict__ pc)
{
    int j = blockIdx.x * 256 + threadIdx.x;
    if (j < B_) g_prog[j] = 0;
    if (j == 0) g_ticket = 0;
    if (j >= B_ * N_) return;
    const float* p = pc + (size_t)j * C_;
    float px = p[0], py = p[1], pz = p[2];
    g_x[j] = px; g_y[j] = py; g_z[j] = pz;
    float tt = __fadd_rn(__fadd_rn(__fmul_rn(px, px), __fmul_rn(py, py)),
                         __fmul_rn(pz, pz));
    g_p4[j] = make_float4(px, py, pz, tt);
}

// ---------------------------------------------------------------------------
// Fused kernel. CTAs 0..15: FPS (one per batch, R5-proven code + release-
// publish of progress). CTAs 16..1039: kNN; each pulls ONE work item from a
// dynamic ticket queue ordered center-block-major (item -> cblk=item>>4,
// b=item&15) — exactly the order items become ready, so resident CTAs never
// convoy on far-future centers. Deadlock-free: FPS CTAs have the lowest
// blockIdx -> wave-1 resident, never wait; every spin terminates.
// ---------------------------------------------------------------------------
#define GC 8

__global__ __launch_bounds__(512, 1)
void fused_kernel(const float* __restrict__ pc, float* __restrict__ out)
{
    // FPS smem
    __shared__ unsigned sb[2][16];
    __shared__ unsigned si[2][16];
    // kNN smem
    __shared__ ull   raw[512][2];          // 8 KB scratch (per-center reuse)
    __shared__ ull   cands[GC][256][2];    // 32 KB merged group candidates
    __shared__ float scq[GC][3];
    __shared__ float sqq[GC];
    __shared__ int   scidx[GC];
    __shared__ int   s_item;

    const int t = threadIdx.x, lane = t & 31, w = t >> 5;

    if (blockIdx.x < B_) {
        // ================= FPS role (R5 verbatim + publish) =================
        const int b = blockIdx.x;
        const int base = b * N_;

        float xs[16], ys[16], zs[16];
#pragma unroll
        for (int i = 0; i < 16; i++) {
            int j = base + t + i * 512;
            xs[i] = g_x[j]; ys[i] = g_y[j]; zs[i] = g_z[j];
        }
        ull xp[8], yp[8], zp[8];
#pragma unroll
        for (int p = 0; p < 8; p++) {
            xp[p] = pk2(xs[2*p], xs[2*p+1]);
            yp[p] = pk2(ys[2*p], ys[2*p+1]);
            zp[p] = pk2(zs[2*p], zs[2*p+1]);
        }
        float dst[16];
#pragma unroll
        for (int i = 0; i < 16; i++) dst[i] = BIGF;

        float qx = g_x[base], qy = g_y[base], qz = g_z[base];
        int cur = 0;
        int* repb = g_rep + b * K_;

        for (int k = 0; k < K_; k++) {
            if (t == 0) {
                repb[k] = cur;
                // release: orders the rep store before the progress increment
                asm volatile("red.release.gpu.global.add.s32 [%0], 1;"
                             :: "l"(g_prog + b) : "memory");
            }

            const ull nqx = pk2(-qx, -qx), nqy = pk2(-qy, -qy), nqz = pk2(-qz, -qz);
            float bv = -1.0f;
#pragma unroll
            for (int p = 0; p < 8; p++) {
                ull dx, dy, dz, s;
                ADD2(dx, xp[p], nqx);
                ADD2(dy, yp[p], nqy);
                ADD2(dz, zp[p], nqz);
                MUL2(dx, dx, dx);
                MUL2(dy, dy, dy);
                MUL2(dz, dz, dz);
                ADD2(s, dx, dy);
                ADD2(s, s, dz);
                float n0 = fminf(dst[2*p],   plo(s)); dst[2*p]   = n0;
                float n1 = fminf(dst[2*p+1], phi(s)); dst[2*p+1] = n1;
                bv = fmaxf(bv, fmaxf(n0, n1));
            }

            const unsigned mybits = __float_as_uint(bv);
            const unsigned mh = __reduce_max_sync(0xffffffffu, mybits);
            unsigned cnd = 0xffffffffu;
            if (mybits == mh) {
                int fi = 0;
#pragma unroll
                for (int i = 15; i >= 0; i--)
                    if (__float_as_uint(dst[i]) == mybits) fi = i;  // smallest i
                cnd = (unsigned)(t + fi * 512);
            }
            const unsigned mi = __reduce_min_sync(0xffffffffu, cnd);

            const int par = k & 1;
            if (lane == 0) { sb[par][w] = mh; si[par][w] = mi; }
            __syncthreads();

            unsigned v  = (lane < 16) ? sb[par][lane] : 0u;
            unsigned i2 = (lane < 16) ? si[par][lane] : 0xffffffffu;
            unsigned Mh = __reduce_max_sync(0xffffffffu, v);
            unsigned c2 = (v == Mh) ? i2 : 0xffffffffu;
            unsigned Mi = __reduce_min_sync(0xffffffffu, c2);
            cur = (int)Mi;

            qx = g_x[base + cur]; qy = g_y[base + cur]; qz = g_z[base + cur];
        }
        return;
    }

    // ================= kNN role =================
    // dynamic work item: ready-order is center-block-major across batches
    if (t == 0) s_item = atomicAdd(&g_ticket, 1);
    __syncthreads();
    const int item = s_item;
    const int b    = item & (B_ - 1);
    const int cen0 = (item >> 4) * GC;
    const int bbase = b * N_;
    const float4* __restrict__ p4 = g_p4 + bbase;

    if (t < GC) {
        // spin until our 8 centers are published (acquire pairs with release)
        const int need = cen0 + GC;
        int v;
        do {
            asm volatile("ld.acquire.gpu.global.s32 %0, [%1];"
                         : "=r"(v) : "l"(g_prog + b) : "memory");
            if (v < need) __nanosleep(256);
        } while (v < need);

        int idx = g_rep[b * K_ + cen0 + t];
        scidx[t] = idx;
        float4 P = p4[idx];
        scq[t][0] = P.x; scq[t][1] = P.y; scq[t][2] = P.z;
        sqq[t] = __fadd_rn(__fadd_rn(__fmul_rn(P.x, P.x), __fmul_rn(P.y, P.y)),
                           __fmul_rn(P.z, P.z));
    }
    __syncthreads();

    // packed per-center-pair constants: (-2*q of center 2pp, -2*q of 2pp+1)
    ull nqx2[4], nqy2[4], nqz2[4], qq2[4];
#pragma unroll
    for (int pp = 0; pp < 4; pp++) {
        nqx2[pp] = pk2(__fmul_rn(-2.0f, scq[2*pp][0]), __fmul_rn(-2.0f, scq[2*pp+1][0]));
        nqy2[pp] = pk2(__fmul_rn(-2.0f, scq[2*pp][1]), __fmul_rn(-2.0f, scq[2*pp+1][1]));
        nqz2[pp] = pk2(__fmul_rn(-2.0f, scq[2*pp][2]), __fmul_rn(-2.0f, scq[2*pp+1][2]));
        qq2[pp]  = pk2(sqq[2*pp], sqq[2*pp+1]);
    }

    float c0d[GC], c1d[GC];
    int   c0i[GC], c1i[GC];
#pragma unroll
    for (int c = 0; c < GC; c++) {
        c0d[c] = FINF; c1d[c] = FINF; c0i[c] = 0x7fffffff; c1i[c] = 0x7fffffff;
    }

    // main loop: 16 points/thread, j strictly increasing, barrier-free
#pragma unroll 4
    for (int i = 0; i < 16; i++) {
        const int j = i * 512 + t;
        const float4 P = __ldg(p4 + j);
        const ull xx = pk2(P.x, P.x), yy = pk2(P.y, P.y);
        const ull zz = pk2(P.z, P.z), ww = pk2(P.w, P.w);
#pragma unroll
        for (int pp = 0; pp < 4; pp++) {
            ull nd, d;
            MUL2(nd, nqx2[pp], xx);
            FMA2(nd, nqy2[pp], yy, nd);
            FMA2(nd, nqz2[pp], zz, nd);    // nd = -2*dot (exact, per center)
            ADD2(d, qq2[pp], nd);          // qq - 2*dot
            ADD2(d, d, ww);                // + tt
            {   // center 2pp  (branchless sorted-insert, strict < = exact ties)
                const int c = 2 * pp;
                const float da = plo(d);
                const bool lt1 = da < c1d[c], lt0 = da < c0d[c];
                const float n1d = lt0 ? c0d[c] : (lt1 ? da : c1d[c]);
                const int   n1i = lt0 ? c0i[c] : (lt1 ? j  : c1i[c]);
                c0d[c] = lt0 ? da : c0d[c];
                c0i[c] = lt0 ? j  : c0i[c];
                c1d[c] = n1d; c1i[c] = n1i;
            }
            {   // center 2pp+1
                const int c = 2 * pp + 1;
                const float db = phi(d);
                const bool lt1 = db < c1d[c], lt0 = db < c0d[c];
                const float n1d = lt0 ? c0d[c] : (lt1 ? db : c1d[c]);
                const int   n1i = lt0 ? c0i[c] : (lt1 ? j  : c1i[c]);
                c0d[c] = lt0 ? db : c0d[c];
                c0i[c] = lt0 ? j  : c0i[c];
                c1d[c] = n1d; c1i[c] = n1i;
            }
        }
    }

    // pair-merge: group g (<256) = threads (g, g+256); exact sorted-2 merge
#pragma unroll
    for (int c = 0; c < GC; c++) {
        raw[t][0] = mkkey(c0d[c], c0i[c]);
        raw[t][1] = mkkey(c1d[c], c1i[c]);
        __syncthreads();
        if (t < 256) {
            ull a0 = raw[t][0],       a1 = raw[t][1];
            ull b0 = raw[t + 256][0], b1 = raw[t + 256][1];
            ull m0 = umin64(a0, b0);
            ull m1 = (a0 < b0) ? umin64(a1, b0) : umin64(b1, a0);
            cands[c][t][0] = m0;
            cands[c][t][1] = m1;
        }
        __syncthreads();
    }

    // ---- selection: warp w (<GC) -> center w; lane owns groups lane*8+o ----
    if (w < GC) {
        const float qx = scq[w][0], qy = scq[w][1], qz = scq[w][2], qq = sqq[w];

        ull fr[GC];
        unsigned stmask = 0;                   // bit o: second candidate consumed
#pragma unroll
        for (int o = 0; o < GC; o++) fr[o] = cands[w][lane * 8 + o][0];

        int selidx = 0;
        for (int r = 0; r < GS_; r++) {
            ull lm = fr[0]; int ow = 0;
#pragma unroll
            for (int o = 1; o < GC; o++) if (fr[o] < lm) { lm = fr[o]; ow = o; }

            unsigned hi  = (unsigned)(lm >> 32);
            unsigned mh  = __reduce_min_sync(0xffffffffu, hi);
            unsigned cnd = (hi == mh) ? (unsigned)lm : 0xffffffffu;
            unsigned mi  = __reduce_min_sync(0xffffffffu, cnd);
            if (lane == r) selidx = (int)mi;

            if (hi == mh && (unsigned)lm == mi) {  // this lane owned the winner
                const int T = lane * 8 + ow;       // group id (<256)
                ull nv;
                if (!((stmask >> ow) & 1u)) {
                    nv = cands[w][T][1];
                    stmask |= 1u << ow;
                } else {
                    // exact refill over the group's 32-pt stream: min key > lm
                    nv = ~0ull;
                    const ull th = lm;
#pragma unroll 4
                    for (int m = 0; m < 16; m++) {
                        int j2 = m * 512 + T;
                        float4 P = __ldg(p4 + j2);
                        float dot = __fmaf_rn(qz, P.z, __fmaf_rn(qy, P.y, __fmul_rn(qx, P.x)));
                        float d2  = __fadd_rn(__fsub_rn(qq, __fmul_rn(2.0f, dot)), P.w);
                        ull key = mkkey(d2, j2);
                        if (key > th && key < nv) nv = key;
                        int j3 = j2 + 256;
                        float4 Q = __ldg(p4 + j3);
                        float dot2 = __fmaf_rn(qz, Q.z, __fmaf_rn(qy, Q.y, __fmul_rn(qx, Q.x)));
                        float e2   = __fadd_rn(__fsub_rn(qq, __fmul_rn(2.0f, dot2)), Q.w);
                        ull key2 = mkkey(e2, j3);
                        if (key2 > th && key2 < nv) nv = key2;
                    }
                }
#pragma unroll
                for (int o = 0; o < GC; o++) if (o == ow) fr[o] = nv;
            }
        }

        // ---- output: lane L holds rank-L neighbor for center w ----
        const int gcen = b * K_ + cen0 + w;
        const int j = selidx;
        const float4 P = __ldg(p4 + j);
        const float* pf = pc + ((size_t)(bbase + j)) * C_;
        float* o6 = out + ((size_t)gcen * GS_ + lane) * C_;
        o6[0] = __fsub_rn(P.x, qx);
        o6[1] = __fsub_rn(P.y, qy);
        o6[2] = __fsub_rn(P.z, qz);
        o6[3] = pf[3];
        o6[4] = pf[4];
        o6[5] = pf[5];
        out[NN_OFF + (size_t)gcen * GS_ + lane] = (float)j;

        // center row (6 channels) for center w
        if (lane == 0) {
            const float* cf = pc + ((size_t)(bbase + scidx[w])) * C_;
            float* co = out + CENTER_OFF + (size_t)gcen * C_;
            co[0] = qx; co[1] = qy; co[2] = qz;
            co[3] = cf[3]; co[4] = cf[4]; co[5] = cf[5];
        }
    }
}

// ---------------------------------------------------------------------------
extern "C" void kernel_launch(void* const* d_in, const int* in_sizes, int n_in,
                              void* d_out, int out_size)
{
    const float* pc = (const float*)d_in[0];
    float* out = (float*)d_out;

    prep_kernel<<<(B_ * N_ + 255) / 256, 256>>>(pc);
    fused_kernel<<<B_ + B_ * K_ / GC, 512>>>(pc, out);
}